// round 1
// baseline (speedup 1.0000x reference)
#include <cuda_runtime.h>
#include <math.h>

// Problem dims
#define T_DIM 512
#define B_DIM 32
#define E_DIM 512
#define H_DIM 2048

// Tiling
#define HC   32            // h channels per CTA
#define NT   96            // 3*HC GEMM columns (z|f|o)
#define MT   128           // T-chunk (rows per GEMM tile)
#define KC   32            // K per smem stage
#define SSTR 36            // smem row stride in words (32 + 4 pad, conflict-free frag loads)

// ---------------- fast math helpers ----------------
__device__ __forceinline__ float ex2f(float x) {
    float y; asm("ex2.approx.f32 %0, %1;" : "=f"(y) : "f"(x)); return y;
}
__device__ __forceinline__ float rcpf(float x) {
    float y; asm("rcp.approx.f32 %0, %1;" : "=f"(y) : "f"(x)); return y;
}
__device__ __forceinline__ unsigned tf32cvt(float x) {
    unsigned y; asm("cvt.rna.tf32.f32 %0, %1;" : "=r"(y) : "f"(x)); return y;
}
__device__ __forceinline__ float sigmoid_fast(float x) {
    // 1 / (1 + e^-x); ex2/rcp approx: rel err ~2^-22. Overflow-safe (inf -> 0).
    float e = ex2f(-1.4426950408889634f * x);
    return rcpf(1.0f + e);
}
__device__ __forceinline__ float tanh_fast(float x) {
    // tanh(x) = 1 - 2/(e^{2x}+1). Saturates correctly for |x| large.
    float e = ex2f(2.8853900817779268f * x);   // e^{2x}
    return 1.0f - 2.0f * rcpf(1.0f + e);
}

__device__ __forceinline__ void mma_tf32(float* c, const unsigned* a, const unsigned* b) {
    asm volatile(
        "mma.sync.aligned.m16n8k8.row.col.f32.tf32.tf32.f32 "
        "{%0,%1,%2,%3}, {%4,%5,%6,%7}, {%8,%9}, {%0,%1,%2,%3};"
        : "+f"(c[0]), "+f"(c[1]), "+f"(c[2]), "+f"(c[3])
        : "r"(a[0]), "r"(a[1]), "r"(a[2]), "r"(a[3]),
          "r"(b[0]), "r"(b[1]));
}

// One CTA = (batch b, 32 h-channels). Fused: TF32 GEMM (512 x 512 x 96) in
// T-chunks of 128, activation into smem, sequential forget-mult scan with
// persistent c/max in registers, final store of embeds[b, h0:h0+32].
__global__ __launch_bounds__(256)
void qrnn_fused_kernel(const float* __restrict__ sent,   // (T, B, E)
                       const float* __restrict__ W,      // (3H, E)
                       const float* __restrict__ bias,   // (3H)
                       float* __restrict__ out)          // (B, H)
{
    const int bb  = blockIdx.y;
    const int h0  = blockIdx.x * HC;
    const int tid = threadIdx.x;
    const int wid  = tid >> 5;
    const int lane = tid & 31;
    const int g  = lane >> 2;    // group id 0..7
    const int tg = lane & 3;     // thread-in-group 0..3
    const int wm = wid & 3;      // warp grid 4(M) x 2(N)
    const int wn = wid >> 2;
    const int m_base = wm * 32;
    const int n_base = wn * 48;

    extern __shared__ unsigned smem_u[];
    unsigned* As = smem_u;                 // MT x SSTR  (tf32 bits)
    unsigned* Bs = smem_u + MT * SSTR;     // NT x SSTR  (tf32 bits)
    float*    act = (float*)smem_u;        // MT x NT floats (aliases staging; disjoint phases)

    // Preload bias for this thread's 6 column-pairs (fixed across chunks)
    float bz0[6], bz1[6];
#pragma unroll
    for (int nf = 0; nf < 6; nf++) {
        int j   = n_base + nf * 8 + tg * 2;
        int grp = j >> 5;                       // 0:z 1:f 2:o
        int idx = grp * H_DIM + h0 + (j & 31);
        bz0[nf] = bias[idx];
        bz1[nf] = bias[idx + 1];
    }

    float c_state = 0.0f;
    float m_state = -INFINITY;

    for (int t0 = 0; t0 < T_DIM; t0 += MT) {
        float acc[2][6][4];
#pragma unroll
        for (int mf = 0; mf < 2; mf++)
#pragma unroll
            for (int nf = 0; nf < 6; nf++)
#pragma unroll
                for (int q = 0; q < 4; q++) acc[mf][nf][q] = 0.0f;

        for (int k0 = 0; k0 < E_DIM; k0 += KC) {
            __syncthreads();   // smem free of previous phase readers

            // --- load A tile: 128 rows x 32 k  (1024 float4, 4/thread) ---
#pragma unroll
            for (int i = 0; i < 4; i++) {
                int lin = i * 256 + tid;
                int m  = lin >> 3;
                int kq = lin & 7;
                const float4 v = *(const float4*)(sent
                    + ((t0 + m) * B_DIM + bb) * E_DIM + k0 + kq * 4);
                unsigned* dst = As + m * SSTR + kq * 4;
                dst[0] = tf32cvt(v.x); dst[1] = tf32cvt(v.y);
                dst[2] = tf32cvt(v.z); dst[3] = tf32cvt(v.w);
            }
            // --- load B tile: 96 rows (cols of W) x 32 k (768 float4, 3/thread) ---
#pragma unroll
            for (int i = 0; i < 3; i++) {
                int lin = i * 256 + tid;
                int j  = lin >> 3;
                int kq = lin & 7;
                int grp = j >> 5;
                int row = grp * H_DIM + h0 + (j & 31);
                const float4 v = *(const float4*)(W + row * E_DIM + k0 + kq * 4);
                unsigned* dst = Bs + j * SSTR + kq * 4;
                dst[0] = tf32cvt(v.x); dst[1] = tf32cvt(v.y);
                dst[2] = tf32cvt(v.z); dst[3] = tf32cvt(v.w);
            }
            __syncthreads();

            // --- compute: 4 k-steps of m16n8k8 ---
#pragma unroll
            for (int ks = 0; ks < 4; ks++) {
                unsigned a[2][4];
#pragma unroll
                for (int mf = 0; mf < 2; mf++) {
                    const unsigned* ap  = As + (m_base + mf * 16 + g) * SSTR + ks * 8 + tg;
                    const unsigned* ap8 = ap + 8 * SSTR;
                    a[mf][0] = ap[0];  a[mf][2] = ap[4];
                    a[mf][1] = ap8[0]; a[mf][3] = ap8[4];
                }
                unsigned bf[6][2];
#pragma unroll
                for (int nf = 0; nf < 6; nf++) {
                    const unsigned* bp = Bs + (n_base + nf * 8 + g) * SSTR + ks * 8 + tg;
                    bf[nf][0] = bp[0];
                    bf[nf][1] = bp[4];
                }
#pragma unroll
                for (int mf = 0; mf < 2; mf++)
#pragma unroll
                    for (int nf = 0; nf < 6; nf++)
                        mma_tf32(acc[mf][nf], a[mf], bf[nf]);
            }
        }

        // --- epilogue: bias + activation -> act[t][j] in smem ---
        __syncthreads();
#pragma unroll
        for (int mf = 0; mf < 2; mf++) {
            int r0 = m_base + mf * 16 + g;
#pragma unroll
            for (int nf = 0; nf < 6; nf++) {
                int j   = n_base + nf * 8 + tg * 2;
                int grp = j >> 5;
#pragma unroll
                for (int rr = 0; rr < 2; rr++) {
                    int row  = r0 + rr * 8;
                    float v0 = acc[mf][nf][rr * 2 + 0] + bz0[nf];
                    float v1 = acc[mf][nf][rr * 2 + 1] + bz1[nf];
                    if (grp == 0) { v0 = tanh_fast(v0);    v1 = tanh_fast(v1); }
                    else          { v0 = sigmoid_fast(v0); v1 = sigmoid_fast(v1); }
                    act[row * NT + j]     = v0;
                    act[row * NT + j + 1] = v1;
                }
            }
        }
        __syncthreads();

        // --- scan: threads 0..31 own one h each; sequential over chunk ---
        if (tid < HC) {
#pragma unroll 8
            for (int t = 0; t < MT; t++) {
                float z = act[t * NT + tid];
                float f = act[t * NT + 32 + tid];
                float o = act[t * NT + 64 + tid];
                c_state = fmaf(f, z - c_state, c_state);   // c = f*z + (1-f)*c
                m_state = fmaxf(m_state, o * c_state);
            }
        }
        // next k-loop's first __syncthreads protects smem reuse
    }

    if (tid < HC) out[bb * H_DIM + h0 + tid] = m_state;
}

extern "C" void kernel_launch(void* const* d_in, const int* in_sizes, int n_in,
                              void* d_out, int out_size)
{
    (void)in_sizes; (void)n_in; (void)out_size;
    const float* sent = (const float*)d_in[0];   // (T,B,E) fp32
    // d_in[1] = lengths (int32) — unused by the math
    const float* W    = (const float*)d_in[2];   // (3H,E) fp32
    const float* bias = (const float*)d_in[3];   // (3H)   fp32
    float* out = (float*)d_out;                  // (B,H)  fp32

    dim3 grid(H_DIM / HC, B_DIM);                // (64, 32)
    qrnn_fused_kernel<<<grid, 256, MT * NT * sizeof(float)>>>(sent, W, bias, out);
}

// round 3
// speedup vs baseline: 2.1378x; 2.1378x over previous
#include <cuda_runtime.h>
#include <cuda_fp16.h>
#include <math.h>
#include <stdint.h>

// Problem dims
#define T_DIM 512
#define B_DIM 32
#define E_DIM 512
#define H_DIM 2048

// Tiling
#define HC  32          // h channels per CTA
#define NT  96          // GEMM N = 3*HC (z|f|o)
#define MT  128         // t-chunk (GEMM M)
#define KC  64          // K elems per smem chunk (fp16 -> 128B rows)
#define NKC 8           // K chunks per t-chunk (512/64)
#define NTC 4           // t-chunks (512/128)
#define NCH (NTC * NKC) // 32 chunks total

#define ACT_STRIDE 100  // act row stride in floats (96 + 4 pad, kills 8-way STS conflicts)

// ---- smem layout (bytes) ----
#define SM_A    0                    // 2 x 16384  (A tiles, fp16 SW128)
#define SM_B    32768                // 2 x 12288  (W tiles, fp16 SW128)
#define SM_ACT  57344                // 128 x 100 x 4 = 51200
#define SM_BIAS 108544               // 96 floats
#define SMEM_BYTES 109056

#define SWZ128(x) ((x) ^ (((x) >> 3) & 0x70))

// fp16 scratch (static device allocations — allowed)
__device__ __half g_sentH[B_DIM * T_DIM * E_DIM];   // (B,T,E) fp16
__device__ __half g_wH[3 * H_DIM * E_DIM];          // (3H,E)  fp16

// ---------------- helpers ----------------
__device__ __forceinline__ uint32_t smem_u32(const void* p) {
    uint32_t a;
    asm("{ .reg .u64 t; cvta.to.shared.u64 t, %1; cvt.u32.u64 %0, t; }" : "=r"(a) : "l"(p));
    return a;
}
__device__ __forceinline__ float ex2f(float x) { float y; asm("ex2.approx.f32 %0, %1;" : "=f"(y) : "f"(x)); return y; }
__device__ __forceinline__ float rcpf(float x) { float y; asm("rcp.approx.f32 %0, %1;" : "=f"(y) : "f"(x)); return y; }
__device__ __forceinline__ float sigmoid_fast(float x) { return rcpf(1.0f + ex2f(-1.4426950408889634f * x)); }
__device__ __forceinline__ float tanh_fast(float x)    { return 1.0f - 2.0f * rcpf(1.0f + ex2f(2.8853900817779268f * x)); }

__device__ __forceinline__ void cp_async16(uint32_t dst, const void* src) {
    uint64_t g; asm("cvta.to.global.u64 %0, %1;" : "=l"(g) : "l"(src));
    asm volatile("cp.async.cg.shared.global [%0], [%1], 16;" :: "r"(dst), "l"(g) : "memory");
}
__device__ __forceinline__ void ldsm4(uint32_t* r, uint32_t addr) {
    asm volatile("ldmatrix.sync.aligned.m8n8.x4.shared.b16 {%0,%1,%2,%3}, [%4];"
                 : "=r"(r[0]), "=r"(r[1]), "=r"(r[2]), "=r"(r[3]) : "r"(addr));
}
__device__ __forceinline__ void mma_f16(float* c, const uint32_t* a, const uint32_t* b) {
    asm volatile(
        "mma.sync.aligned.m16n8k16.row.col.f32.f16.f16.f32 "
        "{%0,%1,%2,%3}, {%4,%5,%6,%7}, {%8,%9}, {%0,%1,%2,%3};"
        : "+f"(c[0]), "+f"(c[1]), "+f"(c[2]), "+f"(c[3])
        : "r"(a[0]), "r"(a[1]), "r"(a[2]), "r"(a[3]), "r"(b[0]), "r"(b[1]));
}

// ---------- prepass: fp32 -> fp16, sent transposed (T,B,E) -> (B,T,E) ----------
__global__ void __launch_bounds__(256) prep_sent(const float* __restrict__ sent) {
    int li = blockIdx.x * 256 + threadIdx.x;         // 2,097,152 float4s
    const float4 v = ((const float4*)sent)[li];
    int e4 = li & 127;
    int b  = (li >> 7) & 31;
    int t  = li >> 12;
    __half2* dst = (__half2*)(g_sentH + ((size_t)(b * T_DIM + t) * E_DIM + e4 * 4));
    dst[0] = __floats2half2_rn(v.x, v.y);
    dst[1] = __floats2half2_rn(v.z, v.w);
}
__global__ void __launch_bounds__(256) prep_w(const float* __restrict__ W) {
    int li = blockIdx.x * 256 + threadIdx.x;         // 786,432 float4s
    const float4 v = ((const float4*)W)[li];
    __half2* dst = (__half2*)g_wH + (size_t)li * 2;
    dst[0] = __floats2half2_rn(v.x, v.y);
    dst[1] = __floats2half2_rn(v.z, v.w);
}

// ---------------- main fused kernel ----------------
__global__ void __launch_bounds__(256, 2)
qrnn_f16_kernel(const float* __restrict__ bias, float* __restrict__ out)
{
    extern __shared__ char smem[];
    const uint32_t sb = smem_u32(smem);
    const int tid = threadIdx.x;
    const int bb  = blockIdx.y;
    const int h0  = blockIdx.x * HC;
    const int lane = tid & 31;
    const int wid  = tid >> 5;
    const int g  = lane >> 2;
    const int tg = lane & 3;
    const int wm = wid & 3;          // 4 warps in M
    const int wn = wid >> 2;         // 2 warps in N
    const int m_base = wm * 32;      // 2 m-tiles of 16
    const int n_base = wn * 48;      // 6 n-tiles of 8

    float* sbias = (float*)(smem + SM_BIAS);
    float* act   = (float*)(smem + SM_ACT);
    if (tid < 96) sbias[tid] = bias[(tid >> 5) * H_DIM + h0 + (tid & 31)];

    const __half* Asrc = g_sentH + (size_t)bb * (T_DIM * E_DIM);

    // precompute per-lane ldmatrix address components
    const int am = lane >> 3;
    const int a_row_in  = (am & 1) * 8 + (lane & 7);       // A: row within 16-row tile
    const int a_colb16  = (am >> 1) * 16;                  // A: 0 or 16 (k half)
    const int b_row_in  = (am >> 1) * 8 + (lane & 7);      // B: n within 16-n pair
    const int b_colb16  = (am & 1) * 16;

    // stage chunk (tc, kc) into buffer buf
    auto stage = [&](int tc, int kc, int buf) {
        const __half* ab = Asrc + (size_t)(tc * MT) * E_DIM + kc * KC;
        const uint32_t aB = sb + SM_A + buf * 16384;
#pragma unroll
        for (int i = 0; i < 4; i++) {
            int l = i * 256 + tid;
            int row = l >> 3, c = l & 7;
            cp_async16(aB + (uint32_t)SWZ128(row * 128 + c * 16), ab + (size_t)row * E_DIM + c * 8);
        }
        const uint32_t bB = sb + SM_B + buf * 12288;
#pragma unroll
        for (int i = 0; i < 3; i++) {
            int l = i * 256 + tid;
            int n = l >> 3, c = l & 7;
            int wrow = (n >> 5) * H_DIM + h0 + (n & 31);
            cp_async16(bB + (uint32_t)SWZ128(n * 128 + c * 16),
                       g_wH + (size_t)wrow * E_DIM + kc * KC + c * 8);
        }
        asm volatile("cp.async.commit_group;" ::: "memory");
    };

    float c_state = 0.0f;
    float m_state = -INFINITY;

    stage(0, 0, 0);

    for (int tc = 0; tc < NTC; tc++) {
        float acc[2][6][4];
#pragma unroll
        for (int mf = 0; mf < 2; mf++)
#pragma unroll
            for (int nf = 0; nf < 6; nf++)
#pragma unroll
                for (int q = 0; q < 4; q++) acc[mf][nf][q] = 0.0f;

        for (int kc = 0; kc < NKC; kc++) {
            const int ch  = tc * NKC + kc;
            const int buf = ch & 1;

            __syncthreads();   // alt buffer's readers (compute of ch-1) are done
            if (ch + 1 < NCH) {
                stage((ch + 1) >> 3, (ch + 1) & 7, (ch + 1) & 1);
                asm volatile("cp.async.wait_group 1;" ::: "memory");
            } else {
                asm volatile("cp.async.wait_group 0;" ::: "memory");
            }
            __syncthreads();   // chunk ch fully staged by all threads

            const uint32_t aB = sb + SM_A + buf * 16384;
            const uint32_t bB = sb + SM_B + buf * 12288;
#pragma unroll
            for (int ks = 0; ks < 4; ks++) {   // 4 k16-steps over KC=64
                uint32_t a[2][4];
#pragma unroll
                for (int mf = 0; mf < 2; mf++) {
                    int row  = m_base + mf * 16 + a_row_in;
                    int colb = ks * 32 + a_colb16;
                    ldsm4(a[mf], aB + (uint32_t)SWZ128(row * 128 + colb));
                }
                uint32_t b[6][2];
#pragma unroll
                for (int p = 0; p < 3; p++) {
                    int nrow = n_base + p * 16 + b_row_in;
                    int colb = ks * 32 + b_colb16;
                    uint32_t r[4];
                    ldsm4(r, bB + (uint32_t)SWZ128(nrow * 128 + colb));
                    b[2 * p][0] = r[0]; b[2 * p][1] = r[1];
                    b[2 * p + 1][0] = r[2]; b[2 * p + 1][1] = r[3];
                }
#pragma unroll
                for (int mf = 0; mf < 2; mf++)
#pragma unroll
                    for (int nf = 0; nf < 6; nf++)
                        mma_f16(acc[mf][nf], a[mf], b[nf]);
            }
        }

        // ---- epilogue: bias + activation -> act ----
        __syncthreads();       // also guarantees scan of tc-1 has finished
#pragma unroll
        for (int mf = 0; mf < 2; mf++) {
            int r0 = m_base + mf * 16 + g;
#pragma unroll
            for (int nf = 0; nf < 6; nf++) {
                int j   = n_base + nf * 8 + tg * 2;
                int grp = j >> 5;
#pragma unroll
                for (int rr = 0; rr < 2; rr++) {
                    int row  = r0 + rr * 8;
                    float v0 = acc[mf][nf][rr * 2 + 0] + sbias[j];
                    float v1 = acc[mf][nf][rr * 2 + 1] + sbias[j + 1];
                    if (grp == 0) { v0 = tanh_fast(v0);    v1 = tanh_fast(v1); }
                    else          { v0 = sigmoid_fast(v0); v1 = sigmoid_fast(v1); }
                    act[row * ACT_STRIDE + j]     = v0;
                    act[row * ACT_STRIDE + j + 1] = v1;
                }
            }
        }
        __syncthreads();

        // ---- scan: threads 0..31, one h each, sequential over the chunk ----
        if (tid < HC) {
#pragma unroll 8
            for (int t = 0; t < MT; t++) {
                float z = act[t * ACT_STRIDE + tid];
                float f = act[t * ACT_STRIDE + 32 + tid];
                float o = act[t * ACT_STRIDE + 64 + tid];
                c_state = fmaf(f, z - c_state, c_state);   // c = f*z + (1-f)*c
                m_state = fmaxf(m_state, o * c_state);
            }
        }
        // next chunk's first __syncthreads orders scan before act overwrite
    }

    if (tid < HC) out[bb * H_DIM + h0 + tid] = m_state;
}

extern "C" void kernel_launch(void* const* d_in, const int* in_sizes, int n_in,
                              void* d_out, int out_size)
{
    (void)in_sizes; (void)n_in; (void)out_size;
    const float* sent = (const float*)d_in[0];   // (T,B,E) fp32
    const float* W    = (const float*)d_in[2];   // (3H,E)  fp32
    const float* bias = (const float*)d_in[3];   // (3H)    fp32
    float* out = (float*)d_out;                  // (B,H)   fp32

    cudaFuncSetAttribute(qrnn_f16_kernel, cudaFuncAttributeMaxDynamicSharedMemorySize, SMEM_BYTES);

    prep_sent<<<8192, 256>>>(sent);
    prep_w<<<3072, 256>>>(W);
    qrnn_f16_kernel<<<dim3(H_DIM / HC, B_DIM), 256, SMEM_BYTES>>>(bias, out);
}

// round 4
// speedup vs baseline: 2.3344x; 1.0920x over previous
#include <cuda_runtime.h>
#include <cuda_fp16.h>
#include <math.h>
#include <stdint.h>

// Problem dims
#define T_DIM 512
#define B_DIM 32
#define E_DIM 512
#define H_DIM 2048

// Tiling
#define HC  32          // h channels per CTA
#define NT  96          // GEMM N = 3*HC (z|f|o)
#define MT  128         // t-chunk (GEMM M)
#define KC  64          // K elems per smem chunk (fp16 -> 128B rows)
#define NKC 8           // K chunks per t-chunk (512/64)
#define NTC 4           // t-chunks (512/128)
#define NCH (NTC * NKC) // 32 chunks total

#define ACT_STRIDE 100  // act row stride in floats

// ---- smem layout (bytes) ----
#define SM_A    0                    // 2 x 16384  (A tiles, fp16 SW128)
#define SM_B    32768                // 2 x 12288  (W tiles, fp16 SW128)
#define SM_ACT  57344                // 128 x 100 x 4 = 51200
#define SM_BIAS 108544               // 96 floats
#define SMEM_BYTES 109056

#define SWZ128(x) ((x) ^ (((x) >> 3) & 0x70))

// fp16 scratch (static device allocations — allowed)
__device__ __half g_sentH[B_DIM * T_DIM * E_DIM];   // (B,T,E) fp16
__device__ __half g_wH[3 * H_DIM * E_DIM];          // (3H,E)  fp16

// ---------------- helpers ----------------
__device__ __forceinline__ uint32_t smem_u32(const void* p) {
    uint32_t a;
    asm("{ .reg .u64 t; cvta.to.shared.u64 t, %1; cvt.u32.u64 %0, t; }" : "=r"(a) : "l"(p));
    return a;
}
__device__ __forceinline__ float tanh_hw(float x) {
    float y; asm("tanh.approx.f32 %0, %1;" : "=f"(y) : "f"(x)); return y;
}
__device__ __forceinline__ float sigmoid_hw(float x) {
    return fmaf(0.5f, tanh_hw(0.5f * x), 0.5f);
}

__device__ __forceinline__ void cp_async16(uint32_t dst, const void* src) {
    uint64_t g; asm("cvta.to.global.u64 %0, %1;" : "=l"(g) : "l"(src));
    asm volatile("cp.async.cg.shared.global [%0], [%1], 16;" :: "r"(dst), "l"(g) : "memory");
}
__device__ __forceinline__ void ldsm4(uint32_t* r, uint32_t addr) {
    asm volatile("ldmatrix.sync.aligned.m8n8.x4.shared.b16 {%0,%1,%2,%3}, [%4];"
                 : "=r"(r[0]), "=r"(r[1]), "=r"(r[2]), "=r"(r[3]) : "r"(addr));
}
__device__ __forceinline__ void mma_f16(float* c, const uint32_t* a, const uint32_t* b) {
    asm volatile(
        "mma.sync.aligned.m16n8k16.row.col.f32.f16.f16.f32 "
        "{%0,%1,%2,%3}, {%4,%5,%6,%7}, {%8,%9}, {%0,%1,%2,%3};"
        : "+f"(c[0]), "+f"(c[1]), "+f"(c[2]), "+f"(c[3])
        : "r"(a[0]), "r"(a[1]), "r"(a[2]), "r"(a[3]), "r"(b[0]), "r"(b[1]));
}

// ---------- merged prepass: fp32 -> fp16; sent also transposed (T,B,E)->(B,T,E) ----------
#define SENT_F4 (T_DIM * B_DIM * E_DIM / 4)   // 2,097,152
#define W_F4    (3 * H_DIM * E_DIM / 4)       //   786,432
__global__ void __launch_bounds__(256) prep_all(const float* __restrict__ sent,
                                                const float* __restrict__ W) {
    int li = blockIdx.x * 256 + threadIdx.x;
    if (li < SENT_F4) {
        const float4 v = ((const float4*)sent)[li];
        int e4 = li & 127;
        int b  = (li >> 7) & 31;
        int t  = li >> 12;
        __half2* dst = (__half2*)(g_sentH + ((size_t)(b * T_DIM + t) * E_DIM + e4 * 4));
        dst[0] = __floats2half2_rn(v.x, v.y);
        dst[1] = __floats2half2_rn(v.z, v.w);
    } else if (li < SENT_F4 + W_F4) {
        int wi = li - SENT_F4;
        const float4 v = ((const float4*)W)[wi];
        __half2* dst = (__half2*)g_wH + (size_t)wi * 2;
        dst[0] = __floats2half2_rn(v.x, v.y);
        dst[1] = __floats2half2_rn(v.z, v.w);
    }
}

// ---------------- main fused kernel: 128 threads, 4 warps (2M x 2N), warp tile 64x48 ----------------
__global__ void __launch_bounds__(128, 2)
qrnn_f16_kernel(const float* __restrict__ bias, float* __restrict__ out)
{
    extern __shared__ char smem[];
    const uint32_t sb = smem_u32(smem);
    const int tid = threadIdx.x;
    const int bb  = blockIdx.y;
    const int h0  = blockIdx.x * HC;
    const int lane = tid & 31;
    const int wid  = tid >> 5;
    const int g  = lane >> 2;
    const int tg = lane & 3;
    const int wm = wid & 1;          // 2 warps in M
    const int wn = wid >> 1;         // 2 warps in N
    const int m_base = wm * 64;      // 4 m-frags of 16
    const int n_base = wn * 48;      // 6 n-frags of 8

    float* sbias = (float*)(smem + SM_BIAS);
    float* act   = (float*)(smem + SM_ACT);
    if (tid < 96) sbias[tid] = bias[(tid >> 5) * H_DIM + h0 + (tid & 31)];

    const __half* Asrc = g_sentH + (size_t)bb * (T_DIM * E_DIM);

    // per-lane ldmatrix address components
    const int am = lane >> 3;
    const int a_row_in = (am & 1) * 8 + (lane & 7);   // row within m16 frag
    const int a_colb16 = (am >> 1) * 16;              // k-half byte offset
    const int b_row_in = (am >> 1) * 8 + (lane & 7);  // n within n16 pair
    const int b_colb16 = (am & 1) * 16;

    // stage chunk (tc, kc) into buffer buf (128 threads)
    auto stage = [&](int tc, int kc, int buf) {
        const __half* ab = Asrc + (size_t)(tc * MT) * E_DIM + kc * KC;
        const uint32_t aB = sb + SM_A + buf * 16384;
#pragma unroll
        for (int i = 0; i < 8; i++) {
            int l = i * 128 + tid;
            int row = l >> 3, c = l & 7;
            cp_async16(aB + (uint32_t)SWZ128(row * 128 + c * 16), ab + (size_t)row * E_DIM + c * 8);
        }
        const uint32_t bB = sb + SM_B + buf * 12288;
#pragma unroll
        for (int i = 0; i < 6; i++) {
            int l = i * 128 + tid;
            int n = l >> 3, c = l & 7;
            int wrow = (n >> 5) * H_DIM + h0 + (n & 31);
            cp_async16(bB + (uint32_t)SWZ128(n * 128 + c * 16),
                       g_wH + (size_t)wrow * E_DIM + kc * KC + c * 8);
        }
        asm volatile("cp.async.commit_group;" ::: "memory");
    };

    float c_state = 0.0f;
    float m_state = -INFINITY;

    stage(0, 0, 0);

    for (int tc = 0; tc < NTC; tc++) {
        float acc[4][6][4];
#pragma unroll
        for (int mf = 0; mf < 4; mf++)
#pragma unroll
            for (int nf = 0; nf < 6; nf++)
#pragma unroll
                for (int q = 0; q < 4; q++) acc[mf][nf][q] = 0.0f;

        for (int kc = 0; kc < NKC; kc++) {
            const int ch  = tc * NKC + kc;
            const int buf = ch & 1;

            __syncthreads();   // alt buffer's MMA readers (chunk ch-1) done
            if (ch + 1 < NCH) {
                stage((ch + 1) >> 3, (ch + 1) & 7, (ch + 1) & 1);
                asm volatile("cp.async.wait_group 1;" ::: "memory");
            } else {
                asm volatile("cp.async.wait_group 0;" ::: "memory");
            }
            __syncthreads();   // chunk ch fully staged

            const uint32_t aB = sb + SM_A + buf * 16384;
            const uint32_t bB = sb + SM_B + buf * 12288;
#pragma unroll
            for (int ks = 0; ks < 4; ks++) {     // 4 k16-steps over KC=64
                uint32_t a[4][4];
#pragma unroll
                for (int mf = 0; mf < 4; mf++) {
                    int row  = m_base + mf * 16 + a_row_in;
                    int colb = ks * 32 + a_colb16;
                    ldsm4(a[mf], aB + (uint32_t)SWZ128(row * 128 + colb));
                }
                uint32_t b[6][2];
#pragma unroll
                for (int p = 0; p < 3; p++) {
                    int nrow = n_base + p * 16 + b_row_in;
                    int colb = ks * 32 + b_colb16;
                    uint32_t r[4];
                    ldsm4(r, bB + (uint32_t)SWZ128(nrow * 128 + colb));
                    b[2 * p][0] = r[0];     b[2 * p][1] = r[1];
                    b[2 * p + 1][0] = r[2]; b[2 * p + 1][1] = r[3];
                }
#pragma unroll
                for (int mf = 0; mf < 4; mf++)
#pragma unroll
                    for (int nf = 0; nf < 6; nf++)
                        mma_f16(acc[mf][nf], a[mf], b[nf]);
            }
        }

        // ---- epilogue: bias + activation -> act ----
        __syncthreads();       // scan of tc-1 finished (it joined the k-loop barriers)
#pragma unroll
        for (int mf = 0; mf < 4; mf++) {
            int r0 = m_base + mf * 16 + g;
#pragma unroll
            for (int nf = 0; nf < 6; nf++) {
                int j   = n_base + nf * 8 + tg * 2;
                int grp = j >> 5;
#pragma unroll
                for (int rr = 0; rr < 2; rr++) {
                    int row  = r0 + rr * 8;
                    float v0 = acc[mf][nf][rr * 2 + 0] + sbias[j];
                    float v1 = acc[mf][nf][rr * 2 + 1] + sbias[j + 1];
                    if (grp == 0) { v0 = tanh_hw(v0);    v1 = tanh_hw(v1); }
                    else          { v0 = sigmoid_hw(v0); v1 = sigmoid_hw(v1); }
                    act[row * ACT_STRIDE + j]     = v0;
                    act[row * ACT_STRIDE + j + 1] = v1;
                }
            }
        }
        __syncthreads();

        // ---- scan: threads 0..31, one h each, sequential over the chunk ----
        if (tid < HC) {
#pragma unroll 8
            for (int t = 0; t < MT; t++) {
                float z = act[t * ACT_STRIDE + tid];
                float f = act[t * ACT_STRIDE + 32 + tid];
                float o = act[t * ACT_STRIDE + 64 + tid];
                c_state = fmaf(f, z - c_state, c_state);   // c = f*z + (1-f)*c
                m_state = fmaxf(m_state, o * c_state);
            }
        }
        // next chunk's first __syncthreads orders scan before act overwrite
    }

    if (tid < HC) out[bb * H_DIM + h0 + tid] = m_state;
}

extern "C" void kernel_launch(void* const* d_in, const int* in_sizes, int n_in,
                              void* d_out, int out_size)
{
    (void)in_sizes; (void)n_in; (void)out_size;
    const float* sent = (const float*)d_in[0];   // (T,B,E) fp32
    const float* W    = (const float*)d_in[2];   // (3H,E)  fp32
    const float* bias = (const float*)d_in[3];   // (3H)    fp32
    float* out = (float*)d_out;                  // (B,H)   fp32

    cudaFuncSetAttribute(qrnn_f16_kernel, cudaFuncAttributeMaxDynamicSharedMemorySize, SMEM_BYTES);

    prep_all<<<(SENT_F4 + W_F4 + 255) / 256, 256>>>(sent, W);
    qrnn_f16_kernel<<<dim3(H_DIM / HC, B_DIM), 128, SMEM_BYTES>>>(bias, out);
}